// round 11
// baseline (speedup 1.0000x reference)
#include <cuda_runtime.h>
#include <cuda_bf16.h>
#include <cstdint>

// Per-row histogram: x[4096,16384] fp32 -> out[4096,30] fp32 (permuted order).
//
// R8 change vs R7: the consumer loop's __syncthreads() is replaced by a
// per-stage "empty" mbarrier (count 4, one elected arrive per warp). R7 hit
// 77% DRAM / 57% issue: per-chunk BAR.SYNC convoyed all 4 warps 8x per row,
// burning ~40% of warp time in barrier machinery. Now warps free-run on their
// own full-barrier waits; only tid0 (producer) waits on empty[s] before
// refilling, with 3 chunks of ring slack.
//
// Pipeline: TMA cp.async.bulk fills a 4-stage x 8KB smem ring; 128 threads
// consume 4x LDS.128 each per stage; counts accumulate in 8 register
// bit-plane CSA counters (cap 255, 128 elem/thread -> unconditionally safe).
// Bin math: t = fma(x,7/3,15); t = min(t,29); k = cvt.rmi.u32(t).

#define NT     128
#define COLS   16384
#define NBINS  30
#define STAGES 4
#define CHUNKB 8192                  // bytes per stage
#define CHUNKS (COLS * 4 / CHUNKB)   // 8 chunks per row

__device__ __forceinline__ uint32_t smem_u32(const void* p) {
    uint32_t a;
    asm("{ .reg .u64 t; cvta.to.shared.u64 t, %1; cvt.u32.u64 %0, t; }"
        : "=r"(a) : "l"(p));
    return a;
}

__device__ __forceinline__ void csa(unsigned& sum, unsigned& carry,
                                    unsigned a, unsigned b, unsigned c) {
    unsigned u = a ^ b;
    sum   = u ^ c;                 // LOP3 0x96
    carry = (a & b) | (u & c);     // LOP3 0xE8
}

__device__ __forceinline__ unsigned bin_onehot(float v) {
    const float SCALE = 2.3333333333333335f;  // 7/3 = 1/binwidth
    const float OFF   = 15.0f;                // 1 - LO/w
    return 1u << __float2uint_rd(fminf(fmaf(v, SCALE, OFF), 29.0f));
}

__device__ __forceinline__ unsigned warp_bit_transpose(unsigned x, int lane) {
    #pragma unroll
    for (int st = 0; st < 5; st++) {
        const int s = 16 >> st;
        const unsigned m = (st == 0) ? 0x0000FFFFu :
                           (st == 1) ? 0x00FF00FFu :
                           (st == 2) ? 0x0F0F0F0Fu :
                           (st == 3) ? 0x33333333u : 0x55555555u;
        unsigned y = __shfl_xor_sync(0xffffffffu, x, s);
        x = (lane & s) ? ((x & ~m) | ((y & ~m) >> s))
                       : ((x &  m) | ((y &  m) << s));
    }
    return x;
}

// Blocking parity wait on an mbarrier.
#define MB_WAIT(mb, parity)                                                   \
    asm volatile(                                                             \
        "{\n\t.reg .pred P;\n"                                                \
        "W%=:\n\t"                                                            \
        "mbarrier.try_wait.parity.acquire.cta.shared::cta.b64 P, [%0], %1, 0x989680;\n\t" \
        "@P bra D%=;\n\t"                                                     \
        "bra W%=;\n"                                                          \
        "D%=:\n\t}"                                                           \
        :: "r"(mb), "r"(parity) : "memory")

__global__ __launch_bounds__(NT)
void hist_kernel(const float* __restrict__ x, float* __restrict__ out) {
    __shared__ __align__(1024) float4 buf[STAGES][CHUNKB / 16];
    __shared__ __align__(8) unsigned long long mbar_full[STAGES];
    __shared__ __align__(8) unsigned long long mbar_empty[STAGES];
    __shared__ unsigned swcnt[NT / 32][32];

    const int tid  = threadIdx.x;
    const int lane = tid & 31;
    const int warp = tid >> 5;
    const int row  = blockIdx.x;

    if (tid == 0) {
        #pragma unroll
        for (int s = 0; s < STAGES; s++) {
            asm volatile("mbarrier.init.shared.b64 [%0], 1;"
                         :: "r"(smem_u32(&mbar_full[s])) : "memory");
            asm volatile("mbarrier.init.shared.b64 [%0], %1;"
                         :: "r"(smem_u32(&mbar_empty[s])), "r"(NT / 32) : "memory");
        }
        asm volatile("fence.proxy.async.shared::cta;" ::: "memory");
    }
    __syncthreads();

    const char* src = reinterpret_cast<const char*>(x + (size_t)row * COLS);

    // Prologue: fill the whole ring.
    if (tid == 0) {
        #pragma unroll
        for (int s = 0; s < STAGES; s++) {
            uint32_t mb = smem_u32(&mbar_full[s]);
            asm volatile("mbarrier.arrive.expect_tx.shared.b64 _, [%0], %1;"
                         :: "r"(mb), "r"(CHUNKB) : "memory");
            asm volatile(
                "cp.async.bulk.shared::cluster.global.mbarrier::complete_tx::bytes"
                " [%0], [%1], %2, [%3];"
                :: "r"(smem_u32(&buf[s][0])), "l"(src + s * CHUNKB),
                   "r"(CHUNKB), "r"(mb) : "memory");
        }
    }

    // 8 bit-plane counters, weights 1..128 (cap 255; 128 elem/thread -> safe)
    unsigned ones = 0, twos = 0, fours = 0;
    unsigned a8 = 0, a16 = 0, a32 = 0, a64 = 0, a128 = 0;

    #pragma unroll 1
    for (int c = 0; c < CHUNKS; c++) {
        const int s = c & (STAGES - 1);
        const unsigned parity = (c / STAGES) & 1u;

        // Wait for TMA fill of stage s (per-thread; warps drift independently).
        MB_WAIT(smem_u32(&mbar_full[s]), parity);

        // Consume 16 elems: 4x LDS.128, conflict-free (lane-contiguous).
        const float4* b = &buf[s][0];
        float4 va = b[tid];
        float4 vb = b[tid + 128];
        float4 vc = b[tid + 256];
        float4 vd = b[tid + 384];

        unsigned h0 = bin_onehot(va.x), h1 = bin_onehot(va.y);
        unsigned h2 = bin_onehot(va.z), h3 = bin_onehot(va.w);
        unsigned h4 = bin_onehot(vb.x), h5 = bin_onehot(vb.y);
        unsigned h6 = bin_onehot(vb.z), h7 = bin_onehot(vb.w);
        unsigned g0 = bin_onehot(vc.x), g1 = bin_onehot(vc.y);
        unsigned g2 = bin_onehot(vc.z), g3 = bin_onehot(vc.w);
        unsigned g4 = bin_onehot(vd.x), g5 = bin_onehot(vd.y);
        unsigned g6 = bin_onehot(vd.z), g7 = bin_onehot(vd.w);

        // All of this warp's reads of stage s are now in registers:
        // signal "empty" (non-blocking) so the producer may refill.
        __syncwarp();
        if (lane == 0)
            asm volatile("mbarrier.arrive.shared.b64 _, [%0];"
                         :: "r"(smem_u32(&mbar_empty[s])) : "memory");

        unsigned c2a, c2b, c4a, c4b, e8a, e8b;
        csa(ones, c2a, ones, h0, h1);
        csa(ones, c2b, ones, h2, h3);
        csa(twos, c4a, twos, c2a, c2b);
        csa(ones, c2a, ones, h4, h5);
        csa(ones, c2b, ones, h6, h7);
        csa(twos, c4b, twos, c2a, c2b);
        csa(fours, e8a, fours, c4a, c4b);
        csa(ones, c2a, ones, g0, g1);
        csa(ones, c2b, ones, g2, g3);
        csa(twos, c4a, twos, c2a, c2b);
        csa(ones, c2a, ones, g4, g5);
        csa(ones, c2b, ones, g6, g7);
        csa(twos, c4b, twos, c2a, c2b);
        csa(fours, e8b, fours, c4a, c4b);
        unsigned c16;
        csa(a8, c16, a8, e8a, e8b);
        unsigned cc = a16 & c16; a16 ^= c16;
        unsigned dd = a32 & cc;  a32 ^= cc;
        cc = a64 & dd;  a64  ^= dd;
        a128 ^= cc;

        // Producer: refill stage s for chunk c+STAGES once all warps signaled.
        if (tid == 0 && c + STAGES < CHUNKS) {
            MB_WAIT(smem_u32(&mbar_empty[s]), parity);
            uint32_t mb = smem_u32(&mbar_full[s]);
            asm volatile("mbarrier.arrive.expect_tx.shared.b64 _, [%0], %1;"
                         :: "r"(mb), "r"(CHUNKB) : "memory");
            asm volatile(
                "cp.async.bulk.shared::cluster.global.mbarrier::complete_tx::bytes"
                " [%0], [%1], %2, [%3];"
                :: "r"(smem_u32(&buf[s][0])), "l"(src + (c + STAGES) * CHUNKB),
                   "r"(CHUNKB), "r"(mb) : "memory");
        }
    }

    // Per-warp: transpose planes so lane b holds bin b; weighted popcounts.
    unsigned planes[8] = {ones, twos, fours, a8, a16, a32, a64, a128};
    unsigned cnt = 0;
    #pragma unroll
    for (int j = 0; j < 8; j++) {
        unsigned t = warp_bit_transpose(planes[j], lane);
        cnt += (unsigned)__popc(t) << j;
    }
    swcnt[warp][lane] = cnt;
    __syncthreads();
    if (warp == 0 && lane < NBINS) {
        unsigned total = swcnt[0][lane] + swcnt[1][lane]
                       + swcnt[2][lane] + swcnt[3][lane];
        int pos = (lane == 0) ? 0 : (lane == NBINS - 1) ? 1 : (lane + 1);
        out[(size_t)row * NBINS + pos] = (float)total;
    }
}

extern "C" void kernel_launch(void* const* d_in, const int* in_sizes, int n_in,
                              void* d_out, int out_size) {
    const float* x = (const float*)d_in[0];
    float* out = (float*)d_out;
    int rows = in_sizes[0] / COLS;
    hist_kernel<<<rows, NT>>>(x, out);
}